// round 1
// baseline (speedup 1.0000x reference)
#include <cuda_runtime.h>
#include <float.h>

// Problem constants (fixed by the reference): B=8, N=2048, D=256, K=8192
#define M_TOTAL 16384          // B*N rows
#define DDIM    256
#define KCODES  8192

// GEMM tiling
#define BM 128
#define BN 128
#define BK 16
#define NKT (DDIM / BK)        // 16 k-tiles
#define NSPLIT 4
#define SPLIT_CODES (KCODES / NSPLIT)   // 2048
#define NT (SPLIT_CODES / BN)           // 16 n-tiles per split
#define AS_STRIDE 132          // 128 + pad (keeps 16B alignment: 132*4=528=33*16)

// Scratch (device globals: no allocations allowed)
__device__ float g_c2[KCODES];
__device__ float g_pval[NSPLIT * M_TOTAL];
__device__ int   g_pidx[NSPLIT * M_TOTAL];
__device__ int   g_idx[M_TOTAL];

// ---------------------------------------------------------------------------
// Kernel 1: c2[k] = ||codebook[k]||^2   (one warp per code)
// ---------------------------------------------------------------------------
__global__ void c2_kernel(const float* __restrict__ cb) {
    int gw   = (blockIdx.x * blockDim.x + threadIdx.x) >> 5;
    int lane = threadIdx.x & 31;
    if (gw >= KCODES) return;
    const float4* row = (const float4*)(cb + (size_t)gw * DDIM);
    float s = 0.f;
#pragma unroll
    for (int i = 0; i < 2; i++) {
        float4 v = row[lane + 32 * i];
        s += v.x * v.x + v.y * v.y + v.z * v.z + v.w * v.w;
    }
#pragma unroll
    for (int o = 16; o > 0; o >>= 1) s += __shfl_xor_sync(0xffffffffu, s, o);
    if (lane == 0) g_c2[gw] = s;
}

// ---------------------------------------------------------------------------
// Kernel 2: fused distance GEMM + per-row argmin over a K-split
//   score(m,n) = c2[n] - 2 * dot(x[m], cb[n])   (z^2 term is row-constant)
// ---------------------------------------------------------------------------
__device__ __forceinline__ void load_tiles(
    float (*As)[AS_STRIDE], float (*Bs)[AS_STRIDE],
    const float* __restrict__ x, const float* __restrict__ cb,
    int mBase, int nBase, int kt, int tid)
{
#pragma unroll
    for (int r = 0; r < 2; r++) {
        int slot = tid + 256 * r;     // 512 float4 slots cover a 16x128 tile
        int m    = slot >> 2;         // 0..127
        int kg   = slot & 3;          // 0..3  (4 floats each)
        float4 av = *(const float4*)(x  + (size_t)(mBase + m) * DDIM + kt * BK + kg * 4);
        As[kg * 4 + 0][m] = av.x;
        As[kg * 4 + 1][m] = av.y;
        As[kg * 4 + 2][m] = av.z;
        As[kg * 4 + 3][m] = av.w;
        float4 bv = *(const float4*)(cb + (size_t)(nBase + m) * DDIM + kt * BK + kg * 4);
        Bs[kg * 4 + 0][m] = bv.x;
        Bs[kg * 4 + 1][m] = bv.y;
        Bs[kg * 4 + 2][m] = bv.z;
        Bs[kg * 4 + 3][m] = bv.w;
    }
}

__global__ void __launch_bounds__(256, 2) vq_argmin_kernel(
    const float* __restrict__ x, const float* __restrict__ cb)
{
    __shared__ float As[2][BK][AS_STRIDE];
    __shared__ float Bs[2][BK][AS_STRIDE];

    const int tid = threadIdx.x;
    const int tx  = tid & 15;          // owns cols tx*8 .. tx*8+7
    const int ty  = tid >> 4;          // owns rows ty*8 .. ty*8+7
    const int mBase      = blockIdx.x * BM;
    const int nSplitBase = blockIdx.y * SPLIT_CODES;

    float best[8];
    int   bidx[8];
#pragma unroll
    for (int i = 0; i < 8; i++) { best[i] = FLT_MAX; bidx[i] = 0; }

    for (int nt = 0; nt < NT; nt++) {
        const int nBase = nSplitBase + nt * BN;

        float acc[8][8];
#pragma unroll
        for (int i = 0; i < 8; i++)
#pragma unroll
            for (int j = 0; j < 8; j++) acc[i][j] = 0.f;

        int buf = 0;
        load_tiles(As[0], Bs[0], x, cb, mBase, nBase, 0, tid);
        __syncthreads();

        for (int kt = 0; kt < NKT; kt++) {
            if (kt + 1 < NKT)
                load_tiles(As[buf ^ 1], Bs[buf ^ 1], x, cb, mBase, nBase, kt + 1, tid);
#pragma unroll
            for (int kk = 0; kk < BK; kk++) {
                float a[8], b[8];
#pragma unroll
                for (int i = 0; i < 8; i++) a[i] = As[buf][kk][ty * 8 + i];
#pragma unroll
                for (int j = 0; j < 8; j++) b[j] = Bs[buf][kk][tx * 8 + j];
#pragma unroll
                for (int i = 0; i < 8; i++)
#pragma unroll
                    for (int j = 0; j < 8; j++)
                        acc[i][j] = fmaf(a[i], b[j], acc[i][j]);
            }
            __syncthreads();
            buf ^= 1;
        }

        // Epilogue: score = c2 - 2*dot, running argmin (ascending n => strict <
        // preserves first-min tie-break)
        float c2v[8];
#pragma unroll
        for (int j = 0; j < 8; j++) c2v[j] = g_c2[nBase + tx * 8 + j];
#pragma unroll
        for (int i = 0; i < 8; i++) {
#pragma unroll
            for (int j = 0; j < 8; j++) {
                float s = fmaf(-2.f, acc[i][j], c2v[j]);
                if (s < best[i]) { best[i] = s; bidx[i] = nBase + tx * 8 + j; }
            }
        }
    }

    // Cross-thread reduction (16 tx per row). Overlay onto As/Bs (done with them;
    // last mainloop iteration ended with __syncthreads()).
    float* rv = &As[0][0][0];          // 128*16 floats = 8KB  (buffer is 16.9KB)
    int*   ri = (int*)&Bs[0][0][0];    // 128*16 ints
#pragma unroll
    for (int i = 0; i < 8; i++) {
        rv[(ty * 8 + i) * 16 + tx] = best[i];
        ri[(ty * 8 + i) * 16 + tx] = bidx[i];
    }
    __syncthreads();

    if (tid < BM) {
        float bv = rv[tid * 16];
        int   bi = ri[tid * 16];
#pragma unroll
        for (int t = 1; t < 16; t++) {
            float v  = rv[tid * 16 + t];
            int   ix = ri[tid * 16 + t];
            if (v < bv || (v == bv && ix < bi)) { bv = v; bi = ix; }
        }
        g_pval[blockIdx.y * M_TOTAL + mBase + tid] = bv;
        g_pidx[blockIdx.y * M_TOTAL + mBase + tid] = bi;
    }
}

// ---------------------------------------------------------------------------
// Kernel 3: combine the NSPLIT partial argmins, emit indices (as float)
// ---------------------------------------------------------------------------
__global__ void combine_kernel(float* __restrict__ out) {
    int m = blockIdx.x * blockDim.x + threadIdx.x;
    if (m >= M_TOTAL) return;
    float bv = g_pval[m];
    int   bi = g_pidx[m];
#pragma unroll
    for (int s = 1; s < NSPLIT; s++) {
        float v  = g_pval[s * M_TOTAL + m];
        int   ix = g_pidx[s * M_TOTAL + m];
        if (v < bv || (v == bv && ix < bi)) { bv = v; bi = ix; }
    }
    g_idx[m] = bi;
    out[(size_t)3 * M_TOTAL * DDIM + m] = (float)bi;   // indices region
}

// ---------------------------------------------------------------------------
// Kernel 4: gather epilogue.  out = [x_recon | z_e | z_q | indices]
//   x_recon = z_q = codebook[idx],  z_e = x
// ---------------------------------------------------------------------------
__global__ void gather_kernel(const float* __restrict__ x,
                              const float* __restrict__ cb,
                              float* __restrict__ out)
{
    const size_t MD4 = (size_t)M_TOTAL * DDIM / 4;   // 1,048,576 float4s per field
    size_t gid = (size_t)blockIdx.x * blockDim.x + threadIdx.x;  // < MD4
    int row = (int)(gid >> 6);     // 64 float4 per row
    int c4  = (int)(gid & 63);
    int idx = g_idx[row];
    float4 cv = ((const float4*)(cb + (size_t)idx * DDIM))[c4];
    float4 xv = ((const float4*)(x  + (size_t)row * DDIM))[c4];
    float4* out4 = (float4*)out;
    out4[gid]           = cv;   // x_recon
    out4[MD4 + gid]     = xv;   // z_e
    out4[2 * MD4 + gid] = cv;   // z_q
}

// ---------------------------------------------------------------------------
extern "C" void kernel_launch(void* const* d_in, const int* in_sizes, int n_in,
                              void* d_out, int out_size) {
    const float* x  = (const float*)d_in[0];   // (8,2048,256) f32
    const float* cb = (const float*)d_in[1];   // (8192,256)  f32
    float* out = (float*)d_out;

    c2_kernel<<<KCODES / 8, 256>>>(cb);                      // 1024 blocks
    dim3 grid(M_TOTAL / BM, NSPLIT);                         // (128, 4)
    vq_argmin_kernel<<<grid, 256>>>(x, cb);
    combine_kernel<<<M_TOTAL / 256, 256>>>(out);             // 64 blocks
    gather_kernel<<<(M_TOTAL * (DDIM / 4)) / 256, 256>>>(x, cb, out);  // 4096 blocks
}

// round 2
// speedup vs baseline: 1.0575x; 1.0575x over previous
#include <cuda_runtime.h>
#include <float.h>

// Problem constants (fixed by the reference): B=8, N=2048, D=256, K=8192
#define M_TOTAL 16384          // B*N rows
#define DDIM    256
#define KCODES  8192

// GEMM tiling
#define BM 128
#define BN 128
#define BK 16
#define NKT (DDIM / BK)        // 16 k-tiles
#define NSPLIT 4
#define SPLIT_CODES (KCODES / NSPLIT)   // 2048
#define NT (SPLIT_CODES / BN)           // 16 n-tiles per split
#define AS_STRIDE 132          // 128 + pad (keeps 16B alignment: 132*4=528=33*16)

// Scratch (device globals: no allocations allowed)
__device__ float g_c2[KCODES];
__device__ float g_pval[NSPLIT * M_TOTAL];
__device__ int   g_pidx[NSPLIT * M_TOTAL];
__device__ int   g_idx[M_TOTAL];

// ---------------------------------------------------------------------------
// Kernel 1: c2[k] = ||codebook[k]||^2   (one warp per code)
// ---------------------------------------------------------------------------
__global__ void c2_kernel(const float* __restrict__ cb) {
    int gw   = (blockIdx.x * blockDim.x + threadIdx.x) >> 5;
    int lane = threadIdx.x & 31;
    if (gw >= KCODES) return;
    const float4* row = (const float4*)(cb + (size_t)gw * DDIM);
    float s = 0.f;
#pragma unroll
    for (int i = 0; i < 2; i++) {
        float4 v = row[lane + 32 * i];
        s += v.x * v.x + v.y * v.y + v.z * v.z + v.w * v.w;
    }
#pragma unroll
    for (int o = 16; o > 0; o >>= 1) s += __shfl_xor_sync(0xffffffffu, s, o);
    if (lane == 0) g_c2[gw] = s;
}

// ---------------------------------------------------------------------------
// Kernel 2: fused distance GEMM + per-row argmin over a K-split
//   score(m,n) = c2[n] - 2 * dot(x[m], cb[n])   (z^2 term is row-constant)
// ---------------------------------------------------------------------------
__device__ __forceinline__ void load_tiles(
    float (*As)[AS_STRIDE], float (*Bs)[AS_STRIDE],
    const float* __restrict__ x, const float* __restrict__ cb,
    int mBase, int nBase, int kt, int tid)
{
#pragma unroll
    for (int r = 0; r < 2; r++) {
        int slot = tid + 256 * r;     // 512 float4 slots cover a 16x128 tile
        int m    = slot >> 2;         // 0..127
        int kg   = slot & 3;          // 0..3  (4 floats each)
        float4 av = *(const float4*)(x  + (size_t)(mBase + m) * DDIM + kt * BK + kg * 4);
        As[kg * 4 + 0][m] = av.x;
        As[kg * 4 + 1][m] = av.y;
        As[kg * 4 + 2][m] = av.z;
        As[kg * 4 + 3][m] = av.w;
        float4 bv = *(const float4*)(cb + (size_t)(nBase + m) * DDIM + kt * BK + kg * 4);
        Bs[kg * 4 + 0][m] = bv.x;
        Bs[kg * 4 + 1][m] = bv.y;
        Bs[kg * 4 + 2][m] = bv.z;
        Bs[kg * 4 + 3][m] = bv.w;
    }
}

__global__ void __launch_bounds__(256, 2) vq_argmin_kernel(
    const float* __restrict__ x, const float* __restrict__ cb)
{
    __shared__ float As[2][BK][AS_STRIDE];
    __shared__ float Bs[2][BK][AS_STRIDE];

    const int tid = threadIdx.x;
    const int tx  = tid & 15;          // owns cols tx*8 .. tx*8+7
    const int ty  = tid >> 4;          // owns rows ty*8 .. ty*8+7
    const int mBase      = blockIdx.x * BM;
    const int nSplitBase = blockIdx.y * SPLIT_CODES;

    float best[8];
    int   bidx[8];
#pragma unroll
    for (int i = 0; i < 8; i++) { best[i] = FLT_MAX; bidx[i] = 0; }

    for (int nt = 0; nt < NT; nt++) {
        const int nBase = nSplitBase + nt * BN;

        float acc[8][8];
#pragma unroll
        for (int i = 0; i < 8; i++)
#pragma unroll
            for (int j = 0; j < 8; j++) acc[i][j] = 0.f;

        int buf = 0;
        load_tiles(As[0], Bs[0], x, cb, mBase, nBase, 0, tid);
        __syncthreads();

        for (int kt = 0; kt < NKT; kt++) {
            if (kt + 1 < NKT)
                load_tiles(As[buf ^ 1], Bs[buf ^ 1], x, cb, mBase, nBase, kt + 1, tid);
#pragma unroll
            for (int kk = 0; kk < BK; kk++) {
                float a[8], b[8];
#pragma unroll
                for (int i = 0; i < 8; i++) a[i] = As[buf][kk][ty * 8 + i];
#pragma unroll
                for (int j = 0; j < 8; j++) b[j] = Bs[buf][kk][tx * 8 + j];
#pragma unroll
                for (int i = 0; i < 8; i++)
#pragma unroll
                    for (int j = 0; j < 8; j++)
                        acc[i][j] = fmaf(a[i], b[j], acc[i][j]);
            }
            __syncthreads();
            buf ^= 1;
        }

        // Epilogue: score = c2 - 2*dot, running argmin (ascending n => strict <
        // preserves first-min tie-break)
        float c2v[8];
#pragma unroll
        for (int j = 0; j < 8; j++) c2v[j] = g_c2[nBase + tx * 8 + j];
#pragma unroll
        for (int i = 0; i < 8; i++) {
#pragma unroll
            for (int j = 0; j < 8; j++) {
                float s = fmaf(-2.f, acc[i][j], c2v[j]);
                if (s < best[i]) { best[i] = s; bidx[i] = nBase + tx * 8 + j; }
            }
        }
    }

    // Cross-thread reduction (16 tx per row). Overlay onto As/Bs (done with them;
    // last mainloop iteration ended with __syncthreads()).
    float* rv = &As[0][0][0];          // 128*16 floats = 8KB  (buffer is 16.9KB)
    int*   ri = (int*)&Bs[0][0][0];    // 128*16 ints
#pragma unroll
    for (int i = 0; i < 8; i++) {
        rv[(ty * 8 + i) * 16 + tx] = best[i];
        ri[(ty * 8 + i) * 16 + tx] = bidx[i];
    }
    __syncthreads();

    if (tid < BM) {
        float bv = rv[tid * 16];
        int   bi = ri[tid * 16];
#pragma unroll
        for (int t = 1; t < 16; t++) {
            float v  = rv[tid * 16 + t];
            int   ix = ri[tid * 16 + t];
            if (v < bv || (v == bv && ix < bi)) { bv = v; bi = ix; }
        }
        g_pval[blockIdx.y * M_TOTAL + mBase + tid] = bv;
        g_pidx[blockIdx.y * M_TOTAL + mBase + tid] = bi;
    }
}

// ---------------------------------------------------------------------------
// Kernel 3: combine the NSPLIT partial argmins, emit indices (as float)
// ---------------------------------------------------------------------------
__global__ void combine_kernel(float* __restrict__ out) {
    int m = blockIdx.x * blockDim.x + threadIdx.x;
    if (m >= M_TOTAL) return;
    float bv = g_pval[m];
    int   bi = g_pidx[m];
#pragma unroll
    for (int s = 1; s < NSPLIT; s++) {
        float v  = g_pval[s * M_TOTAL + m];
        int   ix = g_pidx[s * M_TOTAL + m];
        if (v < bv || (v == bv && ix < bi)) { bv = v; bi = ix; }
    }
    g_idx[m] = bi;
    out[(size_t)3 * M_TOTAL * DDIM + m] = (float)bi;   // indices region
}

// ---------------------------------------------------------------------------
// Kernel 4: gather epilogue.  out = [x_recon | z_e | z_q | indices]
//   x_recon = z_q = codebook[idx],  z_e = x
// ---------------------------------------------------------------------------
__global__ void gather_kernel(const float* __restrict__ x,
                              const float* __restrict__ cb,
                              float* __restrict__ out)
{
    const size_t MD4 = (size_t)M_TOTAL * DDIM / 4;   // 1,048,576 float4s per field
    size_t gid = (size_t)blockIdx.x * blockDim.x + threadIdx.x;  // < MD4
    int row = (int)(gid >> 6);     // 64 float4 per row
    int c4  = (int)(gid & 63);
    int idx = g_idx[row];
    float4 cv = ((const float4*)(cb + (size_t)idx * DDIM))[c4];
    float4 xv = ((const float4*)(x  + (size_t)row * DDIM))[c4];
    float4* out4 = (float4*)out;
    out4[gid]           = cv;   // x_recon
    out4[MD4 + gid]     = xv;   // z_e
    out4[2 * MD4 + gid] = cv;   // z_q
}

// ---------------------------------------------------------------------------
extern "C" void kernel_launch(void* const* d_in, const int* in_sizes, int n_in,
                              void* d_out, int out_size) {
    const float* x  = (const float*)d_in[0];   // (8,2048,256) f32
    const float* cb = (const float*)d_in[1];   // (8192,256)  f32
    float* out = (float*)d_out;

    c2_kernel<<<KCODES / 8, 256>>>(cb);                      // 1024 blocks
    dim3 grid(M_TOTAL / BM, NSPLIT);                         // (128, 4)
    vq_argmin_kernel<<<grid, 256>>>(x, cb);
    combine_kernel<<<M_TOTAL / 256, 256>>>(out);             // 64 blocks
    gather_kernel<<<(M_TOTAL * (DDIM / 4)) / 256, 256>>>(x, cb, out);  // 4096 blocks
}